// round 5
// baseline (speedup 1.0000x reference)
#include <cuda_runtime.h>

// BFP quantize: block = channel vector (C=256) at each (n,h,w), NCHW fp32.
// shape (N=64, C=256, H=56, W=56), HW = 3136 floats = 784 float4.
//
// Tile: 32 hw positions (8 float4 columns) x 256 channels per 512-thread CTA.
// Thread t: hw4 = t & 7 (float4 column), cbase = t >> 3 (0..63),
//           channels c = cbase + 64k, k = 0..3  -> 4 float4 in registers (MLP=4).
// 8 consecutive lanes cover a full 128B line per channel row -> minimal L1
// wavefronts. Single __syncthreads: after the barrier every thread redundantly
// reduces the 16 per-warp partials for its own hw4 and derives the exact
// power-of-two scale via exponent bit arithmetic (no 16-thread serialization,
// no second barrier).

#define THREADS 512
#define CPT 4            // channels per thread = 256 / 64
#define TILE_V4 8        // float4 columns per tile (32 floats of hw)

__device__ __forceinline__ void scale_from_max(float m, float& d, float& iv) {
    // frexp(m) = mant * 2^e; for normal m, e = E - 126 (E = biased exponent).
    // delta = 2^(e-3) = 2^(E-129)  -> biased exp field E-2.
    // inv   = 2^(3-e) = 2^(129-E)  -> biased exp field 256-E.
    unsigned b = __float_as_uint(m);             // m >= 0
    unsigned E = b >> 23;
    if (b == 0u) {
        d = 0.f; iv = 0.f;                       // zero block -> output 0
    } else if (E >= 3u && E <= 253u) {           // fast path
        d  = __uint_as_float((E - 2u)   << 23);
        iv = __uint_as_float((256u - E) << 23);
    } else {                                     // denormal/extreme: exact fallback
        int e;
        (void)frexpf(m, &e);
        d  = ldexpf(1.0f, e - 3);
        iv = ldexpf(1.0f, 3 - e);
    }
}

__global__ void __launch_bounds__(THREADS, 3)
bfp_quant_kernel(const float4* __restrict__ in, float4* __restrict__ out,
                 int hw_v4 /*784*/, int c_dim /*256*/) {
    __shared__ float4 pm4[16][8];   // [warp][hw4] partial maxes

    const int t     = threadIdx.x;
    const int hw4   = t & 7;         // float4 column in tile
    const int cbase = t >> 3;        // 0..63
    const int tile  = blockIdx.x;    // 0..97
    const int n     = blockIdx.y;    // 0..63

    const int base    = n * (c_dim * hw_v4) + cbase * hw_v4 + tile * TILE_V4 + hw4;
    const int cstride = 64 * hw_v4;

    // Front-load 4 independent 16B loads (MLP=4), full-line coalesced.
    float4 v[CPT];
#pragma unroll
    for (int k = 0; k < CPT; k++) v[k] = __ldcs(in + base + k * cstride);

    float4 m;
    m.x = fabsf(v[0].x); m.y = fabsf(v[0].y);
    m.z = fabsf(v[0].z); m.w = fabsf(v[0].w);
#pragma unroll
    for (int k = 1; k < CPT; k++) {
        m.x = fmaxf(m.x, fabsf(v[k].x));
        m.y = fmaxf(m.y, fabsf(v[k].y));
        m.z = fmaxf(m.z, fabsf(v[k].z));
        m.w = fmaxf(m.w, fabsf(v[k].w));
    }

    // Butterfly over the 4 lanes sharing hw4 (xor 8, 16 preserve lane&7).
#pragma unroll
    for (int s = 8; s <= 16; s <<= 1) {
        m.x = fmaxf(m.x, __shfl_xor_sync(0xffffffffu, m.x, s));
        m.y = fmaxf(m.y, __shfl_xor_sync(0xffffffffu, m.y, s));
        m.z = fmaxf(m.z, __shfl_xor_sync(0xffffffffu, m.z, s));
        m.w = fmaxf(m.w, __shfl_xor_sync(0xffffffffu, m.w, s));
    }

    const int w = t >> 5;            // warp id 0..15
    if ((t & 31) < 8) {              // lanes 0..7 hold hw4 = 0..7
        pm4[w][hw4] = m;
    }
    __syncthreads();

    // Every thread redundantly reduces across the 16 warps for its hw4
    // (broadcast LDS, conflict-free) — no second barrier needed.
    float4 mm = pm4[0][hw4];
#pragma unroll
    for (int ww = 1; ww < 16; ww++) {
        float4 b = pm4[ww][hw4];
        mm.x = fmaxf(mm.x, b.x);
        mm.y = fmaxf(mm.y, b.y);
        mm.z = fmaxf(mm.z, b.z);
        mm.w = fmaxf(mm.w, b.w);
    }

    float dx, ix, dy, iy, dz, iz, dw, iw;
    scale_from_max(mm.x, dx, ix);
    scale_from_max(mm.y, dy, iy);
    scale_from_max(mm.z, dz, iz);
    scale_from_max(mm.w, dw, iw);

#pragma unroll
    for (int k = 0; k < CPT; k++) {
        float4 q;
        q.x = truncf(v[k].x * ix) * dx;
        q.y = truncf(v[k].y * iy) * dy;
        q.z = truncf(v[k].z * iz) * dz;
        q.w = truncf(v[k].w * iw) * dw;
        __stcs(out + base + k * cstride, q);
    }
}

extern "C" void kernel_launch(void* const* d_in, const int* in_sizes, int n_in,
                              void* d_out, int out_size) {
    (void)n_in; (void)out_size;
    const float4* in = (const float4*)d_in[0];
    float4* out = (float4*)d_out;

    const int C = 256;
    const int HW = 56 * 56;          // 3136
    const int hw_v4 = HW / 4;        // 784
    const int total = in_sizes[0];   // 51380224
    const int N = total / (C * HW);  // 64

    dim3 grid(hw_v4 / TILE_V4, N);   // (98, 64)
    bfp_quant_kernel<<<grid, THREADS>>>(in, out, hw_v4, C);
}

// round 6
// speedup vs baseline: 1.0966x; 1.0966x over previous
#include <cuda_runtime.h>

// BFP quantize: block = channel vector (C=256) at each (n,h,w), NCHW fp32.
// shape (N=64, C=256, H=56, W=56), HW = 3136 floats = 784 float4.
//
// R4 structure (best: 65.5us): 256-thread CTA, tile = 16 hw (4 float4 cols)
// x 256 channels. Thread t: hw4 = t & 3, cbase = t >> 2 (0..63),
// channels c = cbase + 64k, k = 0..3 -> 4 float4 in regs (MLP=4).
// Two cheap barriers around a 16-thread reduce (that reduce is only ~16
// threads of work — R5 proved distributing it to all threads regresses).
// This round: cap regs for 6 CTAs/SM (48 warps) to deepen phase overlap.

#define THREADS 256
#define CPT 4            // channels per thread = 256 / 64
#define TILE_V4 4        // float4 columns per tile (16 floats of hw)

__global__ void __launch_bounds__(THREADS, 6)
bfp_quant_kernel(const float4* __restrict__ in, float4* __restrict__ out,
                 int hw_v4 /*784*/, int c_dim /*256*/) {
    __shared__ float4 pm4[8][4];    // [warp][hw4] partial maxes (x,y,z,w comps)
    __shared__ float s_delta[16];
    __shared__ float s_inv[16];

    const int t     = threadIdx.x;
    const int hw4   = t & 3;         // float4 column in tile
    const int cbase = t >> 2;        // 0..63
    const int tile  = blockIdx.x;    // 0..195
    const int n     = blockIdx.y;    // 0..63

    const int base    = n * (c_dim * hw_v4) + cbase * hw_v4 + tile * TILE_V4 + hw4;
    const int cstride = 64 * hw_v4;

    // Front-load 4 independent 16B loads (MLP=4).
    float4 v[CPT];
#pragma unroll
    for (int k = 0; k < CPT; k++) v[k] = __ldcs(in + base + k * cstride);

    float mx = fabsf(v[0].x), my = fabsf(v[0].y);
    float mz = fabsf(v[0].z), mw = fabsf(v[0].w);
#pragma unroll
    for (int k = 1; k < CPT; k++) {
        mx = fmaxf(mx, fabsf(v[k].x));
        my = fmaxf(my, fabsf(v[k].y));
        mz = fmaxf(mz, fabsf(v[k].z));
        mw = fmaxf(mw, fabsf(v[k].w));
    }

    // Butterfly over the 8 lanes sharing hw4 (xor 4, 8, 16 preserve lane&3).
#pragma unroll
    for (int s = 4; s <= 16; s <<= 1) {
        mx = fmaxf(mx, __shfl_xor_sync(0xffffffffu, mx, s));
        my = fmaxf(my, __shfl_xor_sync(0xffffffffu, my, s));
        mz = fmaxf(mz, __shfl_xor_sync(0xffffffffu, mz, s));
        mw = fmaxf(mw, __shfl_xor_sync(0xffffffffu, mw, s));
    }

    const int w = t >> 5;            // warp id 0..7
    if ((t & 31) < 4) {              // lanes 0..3 hold hw4 = 0..3
        pm4[w][hw4] = make_float4(mx, my, mz, mw);
    }
    __syncthreads();

    if (t < 16) {                    // t = hw4*4 + comp, scalar hw position
        const float* pm = &pm4[0][0].x;
        float m = pm[t];
#pragma unroll
        for (int ww = 1; ww < 8; ww++) m = fmaxf(m, pm[ww * 16 + t]);

        // frexp(m) = mant * 2^e; for normal m, e = E - 126 (E = biased exp).
        // delta = 2^(e-3) = 2^(E-129) -> exp field E-2.
        // inv   = 2^(3-e) = 2^(129-E) -> exp field 256-E.
        unsigned b = __float_as_uint(m);         // m >= 0
        unsigned E = b >> 23;
        float d, iv;
        if (b == 0u) {
            d = 0.f; iv = 0.f;                   // zero block -> output 0
        } else if (E >= 3u && E <= 253u) {       // fast path
            d  = __uint_as_float((E - 2u)   << 23);
            iv = __uint_as_float((256u - E) << 23);
        } else {                                 // denormal/extreme: exact fallback
            int e;
            (void)frexpf(m, &e);
            d  = ldexpf(1.0f, e - 3);
            iv = ldexpf(1.0f, 3 - e);
        }
        s_delta[t] = d;
        s_inv[t]   = iv;
    }
    __syncthreads();

    const float dx = s_delta[hw4 * 4 + 0], ix = s_inv[hw4 * 4 + 0];
    const float dy = s_delta[hw4 * 4 + 1], iy = s_inv[hw4 * 4 + 1];
    const float dz = s_delta[hw4 * 4 + 2], iz = s_inv[hw4 * 4 + 2];
    const float dw = s_delta[hw4 * 4 + 3], iw = s_inv[hw4 * 4 + 3];

#pragma unroll
    for (int k = 0; k < CPT; k++) {
        float4 q;
        q.x = truncf(v[k].x * ix) * dx;
        q.y = truncf(v[k].y * iy) * dy;
        q.z = truncf(v[k].z * iz) * dz;
        q.w = truncf(v[k].w * iw) * dw;
        __stcs(out + base + k * cstride, q);
    }
}

extern "C" void kernel_launch(void* const* d_in, const int* in_sizes, int n_in,
                              void* d_out, int out_size) {
    (void)n_in; (void)out_size;
    const float4* in = (const float4*)d_in[0];
    float4* out = (float4*)d_out;

    const int C = 256;
    const int HW = 56 * 56;          // 3136
    const int hw_v4 = HW / 4;        // 784
    const int total = in_sizes[0];   // 51380224
    const int N = total / (C * HW);  // 64

    dim3 grid(hw_v4 / TILE_V4, N);   // (196, 64)
    bfp_quant_kernel<<<grid, THREADS>>>(in, out, hw_v4, C);
}

// round 7
// speedup vs baseline: 1.0972x; 1.0005x over previous
#include <cuda_runtime.h>

// BFP quantize: block = channel vector (C=256) at each (n,h,w), NCHW fp32.
// shape (N=64, C=256, H=56, W=56), HW = 3136 floats = 784 float4.
//
// R4 structure (best: 65.5us): 256-thread CTA, tile = 16 hw (4 float4 cols)
// x 256 channels. Thread t: hw4 = t & 3, cbase = t >> 2 (0..63),
// channels c = cbase + 64k, k = 0..3 -> 4 float4 in regs (MLP=4).
// Two cheap barriers around a 16-thread reduce (that reduce is only ~16
// threads of work — R5 proved distributing it to all threads regresses).
// This round: cap regs for 6 CTAs/SM (48 warps) to deepen phase overlap.

#define THREADS 256
#define CPT 4            // channels per thread = 256 / 64
#define TILE_V4 4        // float4 columns per tile (16 floats of hw)

__global__ void __launch_bounds__(THREADS, 6)
bfp_quant_kernel(const float4* __restrict__ in, float4* __restrict__ out,
                 int hw_v4 /*784*/, int c_dim /*256*/) {
    __shared__ float4 pm4[8][4];    // [warp][hw4] partial maxes (x,y,z,w comps)
    __shared__ float s_delta[16];
    __shared__ float s_inv[16];

    const int t     = threadIdx.x;
    const int hw4   = t & 3;         // float4 column in tile
    const int cbase = t >> 2;        // 0..63
    const int tile  = blockIdx.x;    // 0..195
    const int n     = blockIdx.y;    // 0..63

    const int base    = n * (c_dim * hw_v4) + cbase * hw_v4 + tile * TILE_V4 + hw4;
    const int cstride = 64 * hw_v4;

    // Front-load 4 independent 16B loads (MLP=4).
    float4 v[CPT];
#pragma unroll
    for (int k = 0; k < CPT; k++) v[k] = __ldcs(in + base + k * cstride);

    float mx = fabsf(v[0].x), my = fabsf(v[0].y);
    float mz = fabsf(v[0].z), mw = fabsf(v[0].w);
#pragma unroll
    for (int k = 1; k < CPT; k++) {
        mx = fmaxf(mx, fabsf(v[k].x));
        my = fmaxf(my, fabsf(v[k].y));
        mz = fmaxf(mz, fabsf(v[k].z));
        mw = fmaxf(mw, fabsf(v[k].w));
    }

    // Butterfly over the 8 lanes sharing hw4 (xor 4, 8, 16 preserve lane&3).
#pragma unroll
    for (int s = 4; s <= 16; s <<= 1) {
        mx = fmaxf(mx, __shfl_xor_sync(0xffffffffu, mx, s));
        my = fmaxf(my, __shfl_xor_sync(0xffffffffu, my, s));
        mz = fmaxf(mz, __shfl_xor_sync(0xffffffffu, mz, s));
        mw = fmaxf(mw, __shfl_xor_sync(0xffffffffu, mw, s));
    }

    const int w = t >> 5;            // warp id 0..7
    if ((t & 31) < 4) {              // lanes 0..3 hold hw4 = 0..3
        pm4[w][hw4] = make_float4(mx, my, mz, mw);
    }
    __syncthreads();

    if (t < 16) {                    // t = hw4*4 + comp, scalar hw position
        const float* pm = &pm4[0][0].x;
        float m = pm[t];
#pragma unroll
        for (int ww = 1; ww < 8; ww++) m = fmaxf(m, pm[ww * 16 + t]);

        // frexp(m) = mant * 2^e; for normal m, e = E - 126 (E = biased exp).
        // delta = 2^(e-3) = 2^(E-129) -> exp field E-2.
        // inv   = 2^(3-e) = 2^(129-E) -> exp field 256-E.
        unsigned b = __float_as_uint(m);         // m >= 0
        unsigned E = b >> 23;
        float d, iv;
        if (b == 0u) {
            d = 0.f; iv = 0.f;                   // zero block -> output 0
        } else if (E >= 3u && E <= 253u) {       // fast path
            d  = __uint_as_float((E - 2u)   << 23);
            iv = __uint_as_float((256u - E) << 23);
        } else {                                 // denormal/extreme: exact fallback
            int e;
            (void)frexpf(m, &e);
            d  = ldexpf(1.0f, e - 3);
            iv = ldexpf(1.0f, 3 - e);
        }
        s_delta[t] = d;
        s_inv[t]   = iv;
    }
    __syncthreads();

    const float dx = s_delta[hw4 * 4 + 0], ix = s_inv[hw4 * 4 + 0];
    const float dy = s_delta[hw4 * 4 + 1], iy = s_inv[hw4 * 4 + 1];
    const float dz = s_delta[hw4 * 4 + 2], iz = s_inv[hw4 * 4 + 2];
    const float dw = s_delta[hw4 * 4 + 3], iw = s_inv[hw4 * 4 + 3];

#pragma unroll
    for (int k = 0; k < CPT; k++) {
        float4 q;
        q.x = truncf(v[k].x * ix) * dx;
        q.y = truncf(v[k].y * iy) * dy;
        q.z = truncf(v[k].z * iz) * dz;
        q.w = truncf(v[k].w * iw) * dw;
        __stcs(out + base + k * cstride, q);
    }
}

extern "C" void kernel_launch(void* const* d_in, const int* in_sizes, int n_in,
                              void* d_out, int out_size) {
    (void)n_in; (void)out_size;
    const float4* in = (const float4*)d_in[0];
    float4* out = (float4*)d_out;

    const int C = 256;
    const int HW = 56 * 56;          // 3136
    const int hw_v4 = HW / 4;        // 784
    const int total = in_sizes[0];   // 51380224
    const int N = total / (C * HW);  // 64

    dim3 grid(hw_v4 / TILE_V4, N);   // (196, 64)
    bfp_quant_kernel<<<grid, THREADS>>>(in, out, hw_v4, C);
}